// round 7
// baseline (speedup 1.0000x reference)
#include <cuda_runtime.h>
#include <math.h>
#include <stdint.h>

#define DIM 2048
#define NH 16
#define NKV 4
#define HD 128
#define BB 4
#define SS 2048
#define KVD 512        // NKV*HD
#define QKVD 3072      // DIM + 2*KVD
#define MROWS (BB*SS)  // 8192
#define ATTN_SCALE 0.08838834764831845f  // 1/sqrt(128)

// ---------------- scratch (no allocations allowed) ----------------
__device__ float    g_qkv[(size_t)BB*SS*QKVD];     // fp32 gemm outputs
__device__ float    g_q[(size_t)BB*NH*SS*HD];      // tf32 bits (scale folded)
__device__ float    g_k[(size_t)BB*NKV*SS*HD];     // tf32 bits
__device__ float    g_v[(size_t)BB*NKV*SS*HD];     // tf32 bits
__device__ uint32_t g_y[(size_t)BB*SS*DIM];        // tf32 bits, PAIRED layout
__device__ uint32_t g_xt[(size_t)MROWS*DIM];       // tf32 bits of x, PAIRED
__device__ uint32_t g_wt[(size_t)QKVD*DIM];        // tf32 bits Wq|Wk|Wv, PAIRED
__device__ uint32_t g_wpt[(size_t)DIM*DIM];        // tf32 bits Wproj, PAIRED
__device__ float    g_cosr[SS*32];
__device__ float    g_sinr[SS*32];

// =====================================================================
// tf32 helpers
// =====================================================================
__device__ __forceinline__ uint32_t f2tf32(float f) {
    uint32_t r;
    asm("cvt.rna.tf32.f32 %0, %1;" : "=r"(r) : "f"(f));
    return r;
}

__device__ __forceinline__ void mma_tf32(float* c, const uint32_t* a,
                                         uint32_t b0, uint32_t b1) {
    asm volatile(
        "mma.sync.aligned.m16n8k8.row.col.f32.tf32.tf32.f32 "
        "{%0,%1,%2,%3}, {%4,%5,%6,%7}, {%8,%9}, {%0,%1,%2,%3};"
        : "+f"(c[0]), "+f"(c[1]), "+f"(c[2]), "+f"(c[3])
        : "r"(a[0]), "r"(a[1]), "r"(a[2]), "r"(a[3]), "r"(b0), "r"(b1));
}

__device__ __forceinline__ void cpa16(uint32_t dst, const void* src) {
    asm volatile("cp.async.cg.shared.global [%0], [%1], 16;"
                 :: "r"(dst), "l"(src));
}

// =====================================================================
// fp32 -> tf32 bits with per-8-block pairing permutation:
// out block = [k0,k4,k1,k5,k2,k6,k3,k7] so mma fragment (t, t+4) pairs
// are adjacent -> LDS.64 fragment loads in the GEMM.
// one thread handles one 8-word block.
// =====================================================================
__global__ void to_tf32_perm(const float4* __restrict__ src,
                             uint4* __restrict__ dst, int n8)
{
    int i = blockIdx.x * blockDim.x + threadIdx.x;
    if (i < n8) {
        float4 lo = src[2 * i];       // k0..k3
        float4 hi = src[2 * i + 1];   // k4..k7
        dst[2 * i]     = make_uint4(f2tf32(lo.x), f2tf32(hi.x),
                                    f2tf32(lo.y), f2tf32(hi.y));
        dst[2 * i + 1] = make_uint4(f2tf32(lo.z), f2tf32(hi.z),
                                    f2tf32(lo.w), f2tf32(hi.w));
    }
}

// =====================================================================
// tf32 GEMM on pre-converted PAIRED operands. C[m,coloff+n]=sum A[m,k]W[n,k].
// 128x128x32 tiles, cp.async double-buffer, smem stride 40 words
// (stride/2 == 4 mod 16 -> conflict-free LDS.64 for A and B fragments).
// dynamic smem: 2 * 2 * 128*40 words = 81,920 B (2 CTAs/SM).
// =====================================================================
#define SA 40
#define GA(bf) ((bf) * 5120)
#define GB(bf) (10240 + (bf) * 5120)
#define GEMM_SMEM_BYTES 81920

__global__ __launch_bounds__(256, 2)
void gemm_pre(const uint32_t* __restrict__ A, const uint32_t* __restrict__ W,
              float* __restrict__ C, int M, int N, int K, int ldc, int coloff)
{
    extern __shared__ uint32_t sm[];
    const int tid  = threadIdx.x;
    const int lane = tid & 31;
    const int wid  = tid >> 5;
    const int wm   = wid & 3;
    const int wn   = wid >> 2;
    const int g    = lane >> 2;
    const int t    = lane & 3;
    const int m0   = blockIdx.y * 128;
    const int n0   = blockIdx.x * 128;
    const uint32_t smb = (uint32_t)__cvta_generic_to_shared(sm);

    float acc[2][8][4];
#pragma unroll
    for (int mt = 0; mt < 2; mt++)
#pragma unroll
        for (int nt = 0; nt < 8; nt++)
#pragma unroll
            for (int c = 0; c < 4; c++) acc[mt][nt][c] = 0.f;

    const int ntiles = K >> 5;

    // prologue: tile 0 -> buffer 0
#pragma unroll
    for (int r = 0; r < 4; r++) {
        int id = tid + 256 * r;
        int row = id >> 3, c4 = (id & 7) * 4;
        cpa16(smb + (GA(0) + row * SA + c4) * 4, A + (size_t)(m0 + row) * K + c4);
        cpa16(smb + (GB(0) + row * SA + c4) * 4, W + (size_t)(n0 + row) * K + c4);
    }
    asm volatile("cp.async.commit_group;");

    for (int it = 0; it < ntiles; it++) {
        const int bf = it & 1;
        if (it + 1 < ntiles) {
            const int k0 = (it + 1) * 32;
#pragma unroll
            for (int r = 0; r < 4; r++) {
                int id = tid + 256 * r;
                int row = id >> 3, c4 = (id & 7) * 4;
                cpa16(smb + (GA(bf ^ 1) + row * SA + c4) * 4,
                      A + (size_t)(m0 + row) * K + k0 + c4);
                cpa16(smb + (GB(bf ^ 1) + row * SA + c4) * 4,
                      W + (size_t)(n0 + row) * K + k0 + c4);
            }
            asm volatile("cp.async.commit_group;");
            asm volatile("cp.async.wait_group 1;");
        } else {
            asm volatile("cp.async.wait_group 0;");
        }
        __syncthreads();

        const uint32_t* As = sm + GA(bf);
        const uint32_t* Bs = sm + GB(bf);
#pragma unroll
        for (int kc = 0; kc < 4; kc++) {
            const int kb = kc * 8 + 2 * t;
            uint32_t a[2][4];
#pragma unroll
            for (int mt = 0; mt < 2; mt++) {
                int rb = wm * 32 + mt * 16;
                uint2 v0 = *(const uint2*)(As + (rb + g    ) * SA + kb);
                uint2 v1 = *(const uint2*)(As + (rb + g + 8) * SA + kb);
                a[mt][0] = v0.x; a[mt][1] = v1.x;   // k = t
                a[mt][2] = v0.y; a[mt][3] = v1.y;   // k = t+4
            }
#pragma unroll
            for (int nt = 0; nt < 8; nt++) {
                uint2 vb = *(const uint2*)(Bs + (wn * 64 + nt * 8 + g) * SA + kb);
                mma_tf32(acc[0][nt], a[0], vb.x, vb.y);
                mma_tf32(acc[1][nt], a[1], vb.x, vb.y);
            }
        }
        __syncthreads();
    }

#pragma unroll
    for (int mt = 0; mt < 2; mt++) {
        int row = m0 + wm * 32 + mt * 16 + g;
#pragma unroll
        for (int nt = 0; nt < 8; nt++) {
            int col = coloff + n0 + wn * 64 + nt * 8 + 2 * t;
            float2 v01 = make_float2(acc[mt][nt][0], acc[mt][nt][1]);
            float2 v23 = make_float2(acc[mt][nt][2], acc[mt][nt][3]);
            *(float2*)(C + (size_t)row * ldc + col)       = v01;
            *(float2*)(C + (size_t)(row + 8) * ldc + col) = v23;
        }
    }
}

// =====================================================================
// RoPE table init
// =====================================================================
__global__ void rope_init()
{
    int i = blockIdx.x * blockDim.x + threadIdx.x;
    int s = i >> 5, f = i & 31;
    double inv = pow(10000.0, -(double)f / 32.0);
    double ang = (double)s * inv;
    double sd, cd;
    sincos(ang, &sd, &cd);
    g_cosr[i] = (float)cd;
    g_sinr[i] = (float)sd;
}

// =====================================================================
// RMS-norm + RoPE + gain + reshape; q/k/v stored as tf32 bits (unpaired)
// =====================================================================
__global__ void norm_rope(const float* __restrict__ qkv,
                          const float* __restrict__ q_gain,
                          float* __restrict__ q, float* __restrict__ k,
                          float* __restrict__ v)
{
    const int bs   = blockIdx.x;
    const int head = blockIdx.y;
    const int b = bs / SS, s = bs % SS;
    const int d = threadIdx.x;

    if (head >= NH + NKV) {
        int kv = head - NH - NKV;
        float val = qkv[(size_t)bs * QKVD + DIM + KVD + kv * HD + d];
        v[((size_t)(b * NKV + kv) * SS + s) * HD + d] = __uint_as_float(f2tf32(val));
        return;
    }
    const bool isq = (head < NH);
    const float* row = qkv + (size_t)bs * QKVD +
                       (isq ? head * HD : DIM + (head - NH) * HD);
    float val = row[d];

    __shared__ float red[4];
    __shared__ float xs[HD];
    float sq = val * val;
#pragma unroll
    for (int o = 16; o > 0; o >>= 1) sq += __shfl_xor_sync(0xffffffffu, sq, o);
    if ((d & 31) == 0) red[d >> 5] = sq;
    __syncthreads();
    float ms = (red[0] + red[1] + red[2] + red[3]) * (1.0f / HD);
    float xn = val * rsqrtf(ms + 1.1920929e-07f);
    xs[d] = xn;
    __syncthreads();

    float outv;
    if (d < 64) {
        int f = d & 31;
        float c  = g_cosr[s * 32 + f];
        float sn = g_sinr[s * 32 + f];
        float x1 = xs[f], x2 = xs[f + 32];
        outv = (d < 32) ? (x1 * c + x2 * sn) : (-x1 * sn + x2 * c);
    } else {
        outv = xn;
    }

    if (isq) {
        outv *= q_gain[head] * ATTN_SCALE;
        q[((size_t)(b * NH + head) * SS + s) * HD + d] = __uint_as_float(f2tf32(outv));
    } else {
        int kv = head - NH;
        k[((size_t)(b * NKV + kv) * SS + s) * HD + d] = __uint_as_float(f2tf32(outv));
    }
}

// =====================================================================
// tf32 flash attention (same as R5; epilogue emits PAIRED tf32 y)
// =====================================================================
#define QS_OFF   0            // 128 x 132
#define KS_OFF   16896        // 64 x 132
#define VS_OFF0  25344        // 64 x 136
#define VS_OFF1  34048
#define PS_OFF   42752        // 128 x 68
#define PMAX_OFF 51456        // [2][128]
#define PSUM_OFF 51712        // [2][128]
#define MS_OFF   51968        // [128]
#define LS_OFF   52096        // [128]
#define ATTN_WORDS 52224      // 208,896 bytes

__global__ __launch_bounds__(256, 1)
void attn_mma(const float* __restrict__ q, const float* __restrict__ k,
              const float* __restrict__ v, uint32_t* __restrict__ y)
{
    extern __shared__ uint32_t sm[];
    const int qb = (int)gridDim.x - 1 - (int)blockIdx.x;
    const int h = blockIdx.y, b = blockIdx.z;
    const int kvh = h >> 2;
    const int tid = threadIdx.x;
    const int lane = tid & 31, wid = tid >> 5;
    const int g = lane >> 2, t = lane & 3;
    const int wm = wid & 3, wn = wid >> 2;
    const int bar_id = 1 + wm;

    const float* qbase = q + ((size_t)(b * NH + h) * SS + (size_t)qb * 128) * HD;
    const float* kbase = k + ((size_t)(b * NKV + kvh) * SS) * HD;
    const float* vbase = v + ((size_t)(b * NKV + kvh) * SS) * HD;

    const uint32_t smb = (uint32_t)__cvta_generic_to_shared(sm);

    float* m_s  = (float*)(sm + MS_OFF);
    float* l_s  = (float*)(sm + LS_OFF);
    float* pmax = (float*)(sm + PMAX_OFF);
    float* psum = (float*)(sm + PSUM_OFF);

#pragma unroll
    for (int i = 0; i < 16; i++) {
        int id = tid + 256 * i;
        int row = id >> 5, c4 = (id & 31) * 4;
        cpa16(smb + (QS_OFF + row * 132 + c4) * 4, qbase + (size_t)row * HD + c4);
    }
#pragma unroll
    for (int i = 0; i < 8; i++) {
        int id = tid + 256 * i;
        int row = id >> 5, c4 = (id & 31) * 4;
        cpa16(smb + (KS_OFF + row * 132 + c4) * 4, kbase + (size_t)row * HD + c4);
        cpa16(smb + (VS_OFF0 + row * 136 + c4) * 4, vbase + (size_t)row * HD + c4);
    }
    asm volatile("cp.async.commit_group;");

    if (tid < 128) { m_s[tid] = -1e30f; l_s[tid] = 0.f; }

    float oacc[2][8][4];
#pragma unroll
    for (int mt = 0; mt < 2; mt++)
#pragma unroll
        for (int nt = 0; nt < 8; nt++)
#pragma unroll
            for (int c = 0; c < 4; c++) oacc[mt][nt][c] = 0.f;

    const int nkv = 2 * qb + 2;

    asm volatile("cp.async.wait_group 0;");
    __syncthreads();

    for (int kvt = 0; kvt < nkv; kvt++) {
        const int cur = kvt & 1;

        float sacc[2][4][4];
#pragma unroll
        for (int mt = 0; mt < 2; mt++)
#pragma unroll
            for (int nt = 0; nt < 4; nt++)
#pragma unroll
                for (int c = 0; c < 4; c++) sacc[mt][nt][c] = 0.f;

        const uint32_t* Qb = sm + QS_OFF + (wm * 32) * 132;
        const uint32_t* Kb = sm + KS_OFF + (wn * 32) * 132;
#pragma unroll
        for (int ks = 0; ks < 16; ks++) {
            const int kb = ks * 8;
            uint32_t a[2][4];
#pragma unroll
            for (int mt = 0; mt < 2; mt++) {
                const uint32_t* Qr = Qb + mt * 16 * 132;
                a[mt][0] = Qr[g * 132 + kb + t];
                a[mt][1] = Qr[(g + 8) * 132 + kb + t];
                a[mt][2] = Qr[g * 132 + kb + t + 4];
                a[mt][3] = Qr[(g + 8) * 132 + kb + t + 4];
            }
#pragma unroll
            for (int nt = 0; nt < 4; nt++) {
                uint32_t b0 = Kb[(nt * 8 + g) * 132 + kb + t];
                uint32_t b1 = Kb[(nt * 8 + g) * 132 + kb + t + 4];
                mma_tf32(sacc[0][nt], a[0], b0, b1);
                mma_tf32(sacc[1][nt], a[1], b0, b1);
            }
        }

        if (kvt >= 2 * qb) {
            const int off = (kvt - 2 * qb) * 64;
#pragma unroll
            for (int mt = 0; mt < 2; mt++) {
                int r0 = wm * 32 + mt * 16 + g, r1 = r0 + 8;
#pragma unroll
                for (int nt = 0; nt < 4; nt++) {
                    int c = wn * 32 + nt * 8 + 2 * t + off;
                    if (c     > r0) sacc[mt][nt][0] = -1e30f;
                    if (c + 1 > r0) sacc[mt][nt][1] = -1e30f;
                    if (c     > r1) sacc[mt][nt][2] = -1e30f;
                    if (c + 1 > r1) sacc[mt][nt][3] = -1e30f;
                }
            }
        }

#pragma unroll
        for (int mt = 0; mt < 2; mt++) {
            float rm0 = -1e30f, rm1 = -1e30f;
#pragma unroll
            for (int nt = 0; nt < 4; nt++) {
                rm0 = fmaxf(rm0, fmaxf(sacc[mt][nt][0], sacc[mt][nt][1]));
                rm1 = fmaxf(rm1, fmaxf(sacc[mt][nt][2], sacc[mt][nt][3]));
            }
            rm0 = fmaxf(rm0, __shfl_xor_sync(0xffffffffu, rm0, 1));
            rm0 = fmaxf(rm0, __shfl_xor_sync(0xffffffffu, rm0, 2));
            rm1 = fmaxf(rm1, __shfl_xor_sync(0xffffffffu, rm1, 1));
            rm1 = fmaxf(rm1, __shfl_xor_sync(0xffffffffu, rm1, 2));
            if (t == 0) {
                pmax[wn * 128 + wm * 32 + mt * 16 + g]     = rm0;
                pmax[wn * 128 + wm * 32 + mt * 16 + g + 8] = rm1;
            }
        }
        asm volatile("bar.sync %0, 64;" :: "r"(bar_id) : "memory");

        float alpha[2][2], mnew[2][2];
#pragma unroll
        for (int mt = 0; mt < 2; mt++) {
            int r0 = wm * 32 + mt * 16 + g, r1 = r0 + 8;
            float mo0 = m_s[r0], mo1 = m_s[r1];
            float mn0 = fmaxf(mo0, fmaxf(pmax[r0], pmax[128 + r0]));
            float mn1 = fmaxf(mo1, fmaxf(pmax[r1], pmax[128 + r1]));
            alpha[mt][0] = __expf(mo0 - mn0);
            alpha[mt][1] = __expf(mo1 - mn1);
            mnew[mt][0] = mn0; mnew[mt][1] = mn1;
            float rs0 = 0.f, rs1 = 0.f;
#pragma unroll
            for (int nt = 0; nt < 4; nt++) {
                float p00 = __expf(sacc[mt][nt][0] - mn0);
                float p01 = __expf(sacc[mt][nt][1] - mn0);
                float p10 = __expf(sacc[mt][nt][2] - mn1);
                float p11 = __expf(sacc[mt][nt][3] - mn1);
                rs0 += p00 + p01;
                rs1 += p10 + p11;
                int col = wn * 32 + nt * 8 + 2 * t;
                *(uint2*)(sm + PS_OFF + r0 * 68 + col) = make_uint2(f2tf32(p00), f2tf32(p01));
                *(uint2*)(sm + PS_OFF + r1 * 68 + col) = make_uint2(f2tf32(p10), f2tf32(p11));
            }
            rs0 += __shfl_xor_sync(0xffffffffu, rs0, 1);
            rs0 += __shfl_xor_sync(0xffffffffu, rs0, 2);
            rs1 += __shfl_xor_sync(0xffffffffu, rs1, 1);
            rs1 += __shfl_xor_sync(0xffffffffu, rs1, 2);
            if (t == 0) {
                psum[wn * 128 + r0] = rs0;
                psum[wn * 128 + r1] = rs1;
            }
        }
#pragma unroll
        for (int mt = 0; mt < 2; mt++)
#pragma unroll
            for (int nt = 0; nt < 8; nt++) {
                oacc[mt][nt][0] *= alpha[mt][0];
                oacc[mt][nt][1] *= alpha[mt][0];
                oacc[mt][nt][2] *= alpha[mt][1];
                oacc[mt][nt][3] *= alpha[mt][1];
            }
        asm volatile("bar.sync %0, 64;" :: "r"(bar_id) : "memory");
        if (wn == 0 && t == 0) {
#pragma unroll
            for (int mt = 0; mt < 2; mt++) {
                int r0 = wm * 32 + mt * 16 + g, r1 = r0 + 8;
                l_s[r0] = l_s[r0] * alpha[mt][0] + psum[r0] + psum[128 + r0];
                l_s[r1] = l_s[r1] * alpha[mt][1] + psum[r1] + psum[128 + r1];
                m_s[r0] = mnew[mt][0];
                m_s[r1] = mnew[mt][1];
            }
        }

        __syncthreads();
        if (kvt + 1 < nkv) {
            const float* kn = kbase + (size_t)(kvt + 1) * 64 * HD;
            const float* vn = vbase + (size_t)(kvt + 1) * 64 * HD;
            const uint32_t vo = cur ? VS_OFF0 : VS_OFF1;
#pragma unroll
            for (int i = 0; i < 8; i++) {
                int id = tid + 256 * i;
                int row = id >> 5, c4 = (id & 31) * 4;
                cpa16(smb + (KS_OFF + row * 132 + c4) * 4, kn + (size_t)row * HD + c4);
                cpa16(smb + (vo + row * 136 + c4) * 4, vn + (size_t)row * HD + c4);
            }
            asm volatile("cp.async.commit_group;");
        }

        const uint32_t* Pb = sm + PS_OFF + (wm * 32) * 68;
        const uint32_t* Vb = sm + (cur ? VS_OFF1 : VS_OFF0) + wn * 64;
#pragma unroll
        for (int ks = 0; ks < 8; ks++) {
            const int kb = ks * 8;
            uint32_t a[2][4];
#pragma unroll
            for (int mt = 0; mt < 2; mt++) {
                const uint32_t* Pr = Pb + mt * 16 * 68;
                a[mt][0] = Pr[g * 68 + kb + t];
                a[mt][1] = Pr[(g + 8) * 68 + kb + t];
                a[mt][2] = Pr[g * 68 + kb + t + 4];
                a[mt][3] = Pr[(g + 8) * 68 + kb + t + 4];
            }
#pragma unroll
            for (int nt = 0; nt < 8; nt++) {
                uint32_t b0 = Vb[(kb + t) * 136 + nt * 8 + g];
                uint32_t b1 = Vb[(kb + t + 4) * 136 + nt * 8 + g];
                mma_tf32(oacc[0][nt], a[0], b0, b1);
                mma_tf32(oacc[1][nt], a[1], b0, b1);
            }
        }

        if (kvt + 1 < nkv) {
            asm volatile("cp.async.wait_group 0;");
            __syncthreads();
        }
    }

    asm volatile("bar.sync %0, 64;" :: "r"(bar_id) : "memory");

    // ---- epilogue: normalize, emit PAIRED tf32 bits for the proj gemm ----
    // local positions inside each 8-col block for (c1=2t, c2=2t+1):
    const int p1 = 2 * ((2 * t) & 3) + (t >> 1);
    const int p2 = 2 * ((2 * t + 1) & 3) + (t >> 1);
#pragma unroll
    for (int mt = 0; mt < 2; mt++) {
        int r0 = wm * 32 + mt * 16 + g, r1 = r0 + 8;
        float linv0 = 1.0f / l_s[r0];
        float linv1 = 1.0f / l_s[r1];
        uint32_t* y0 = y + ((size_t)b * SS + (size_t)qb * 128 + r0) * DIM + h * HD + wn * 64;
        uint32_t* y1 = y + ((size_t)b * SS + (size_t)qb * 128 + r1) * DIM + h * HD + wn * 64;
#pragma unroll
        for (int nt = 0; nt < 8; nt++) {
            int base = nt * 8;
            y0[base + p1] = f2tf32(oacc[mt][nt][0] * linv0);
            y0[base + p2] = f2tf32(oacc[mt][nt][1] * linv0);
            y1[base + p1] = f2tf32(oacc[mt][nt][2] * linv1);
            y1[base + p2] = f2tf32(oacc[mt][nt][3] * linv1);
        }
    }
}

// =====================================================================
// host
// =====================================================================
extern "C" void kernel_launch(void* const* d_in, const int* in_sizes, int n_in,
                              void* d_out, int out_size)
{
    const float* x     = (const float*)d_in[0];
    const float* Wq    = (const float*)d_in[1];
    const float* Wk    = (const float*)d_in[2];
    const float* Wv    = (const float*)d_in[3];
    const float* Wproj = (const float*)d_in[4];
    const float* qg    = (const float*)d_in[5];
    float* out = (float*)d_out;

    float *qkv, *q, *k, *v;
    uint32_t *y, *xt, *wt, *wpt;
    cudaGetSymbolAddress((void**)&qkv, g_qkv);
    cudaGetSymbolAddress((void**)&q,   g_q);
    cudaGetSymbolAddress((void**)&k,   g_k);
    cudaGetSymbolAddress((void**)&v,   g_v);
    cudaGetSymbolAddress((void**)&y,   g_y);
    cudaGetSymbolAddress((void**)&xt,  g_xt);
    cudaGetSymbolAddress((void**)&wt,  g_wt);
    cudaGetSymbolAddress((void**)&wpt, g_wpt);

    cudaFuncSetAttribute(attn_mma,
                         cudaFuncAttributeMaxDynamicSharedMemorySize,
                         ATTN_WORDS * sizeof(uint32_t));
    cudaFuncSetAttribute(gemm_pre,
                         cudaFuncAttributeMaxDynamicSharedMemorySize,
                         GEMM_SMEM_BYTES);

    // 0) RoPE tables + paired tf32 pre-conversions
    rope_init<<<SS * 32 / 256, 256>>>();
    to_tf32_perm<<<(MROWS * DIM / 8 + 255) / 256, 256>>>((const float4*)x, (uint4*)xt, MROWS * DIM / 8);
    to_tf32_perm<<<(DIM * DIM / 8 + 255) / 256, 256>>>((const float4*)Wq, (uint4*)wt, DIM * DIM / 8);
    to_tf32_perm<<<(KVD * DIM / 8 + 255) / 256, 256>>>((const float4*)Wk, (uint4*)(wt + (size_t)DIM * DIM), KVD * DIM / 8);
    to_tf32_perm<<<(KVD * DIM / 8 + 255) / 256, 256>>>((const float4*)Wv, (uint4*)(wt + (size_t)(DIM + KVD) * DIM), KVD * DIM / 8);
    to_tf32_perm<<<(DIM * DIM / 8 + 255) / 256, 256>>>((const float4*)Wproj, (uint4*)wpt, DIM * DIM / 8);

    // 1) ALL QKV projections in ONE launch (N = 3072)
    gemm_pre<<<dim3(QKVD / 128, MROWS / 128), 256, GEMM_SMEM_BYTES>>>(
        xt, wt, qkv, MROWS, QKVD, DIM, QKVD, 0);

    // 2) RMS-norm + RoPE + gain + reshape (tf32 outputs)
    norm_rope<<<dim3(BB * SS, NH + 2 * NKV), 128>>>(qkv, qg, q, k, v);

    // 3) flash attention (Q tile 128) -> g_y (paired tf32 bits)
    attn_mma<<<dim3(SS / 128, NH, BB), 256,
               ATTN_WORDS * sizeof(uint32_t)>>>(q, k, v, y);

    // 4) output projection -> d_out
    gemm_pre<<<dim3(DIM / 128, MROWS / 128), 256, GEMM_SMEM_BYTES>>>(
        y, wpt, out, MROWS, DIM, DIM, DIM, 0);
}